// round 12
// baseline (speedup 1.0000x reference)
#include <cuda_runtime.h>
#include <cuda_bf16.h>
#include <cstdint>

// Problem constants: N=512, A=1024, B=64, C=16
#define NN   512
#define AA   1024
#define BB   64
#define CC   16
#define OUTW (AA + BB)   // 1088

#define NGRP   16            // row groups of 32
#define GSZ    32
#define NTILES (NGRP * (NGRP + 1) / 2)   // 136

#define LOG2E 1.44269504088896340736f

// ---------------- device scratch ----------------
// M quantized to int8 in log2e units: g_Mq row stride 1024 B, [row][b*16 + c]
__device__ uint32_t g_Mq[NN * 256];
__device__ __nv_bfloat16 g_xb[NN * AA];     // x in bf16
__device__ __nv_bfloat16 g_Wb[AA * AA];     // W * log2e in bf16, native [k][n]

// ---------------- helpers ----------------
__device__ __forceinline__ uint32_t smem_u32(const void* p) {
    uint32_t a;
    asm("{ .reg .u64 t; cvta.to.shared.u64 t, %1; cvt.u32.u64 %0, t; }" : "=r"(a) : "l"(p));
    return a;
}
#define LDMATRIX_X4(r0, r1, r2, r3, addr) \
    asm volatile("ldmatrix.sync.aligned.m8n8.x4.shared.b16 {%0,%1,%2,%3}, [%4];" \
        : "=r"(r0), "=r"(r1), "=r"(r2), "=r"(r3) : "r"(addr))
#define LDMATRIX_X4_T(r0, r1, r2, r3, addr) \
    asm volatile("ldmatrix.sync.aligned.m8n8.x4.trans.shared.b16 {%0,%1,%2,%3}, [%4];" \
        : "=r"(r0), "=r"(r1), "=r"(r2), "=r"(r3) : "r"(addr))

__device__ __forceinline__ void mma_bf16(float d[4], const uint32_t a[4], const uint32_t b[2]) {
    asm volatile(
        "mma.sync.aligned.m16n8k16.row.col.f32.bf16.bf16.f32 "
        "{%0,%1,%2,%3}, {%4,%5,%6,%7}, {%8,%9}, {%0,%1,%2,%3};"
        : "+f"(d[0]), "+f"(d[1]), "+f"(d[2]), "+f"(d[3])
        : "r"(a[0]), "r"(a[1]), "r"(a[2]), "r"(a[3]), "r"(b[0]), "r"(b[1]));
}

__device__ __forceinline__ __nv_bfloat162 u2b(uint32_t u) {
    return *reinterpret_cast<__nv_bfloat162*>(&u);
}
__device__ __forceinline__ uint32_t b2u(__nv_bfloat162 v) {
    return *reinterpret_cast<uint32_t*>(&v);
}
__device__ __forceinline__ float ex2(float v) {
    float r; asm("ex2.approx.f32 %0, %1;" : "=f"(r) : "f"(v)); return r;
}
// packed byte SAD with accumulate: d = sum_i |a_i - b_i| + c  (signed bytes)
__device__ __forceinline__ int vsad4(uint32_t a, uint32_t b, int c) {
    int d;
    asm("vabsdiff4.s32.s32.s32.add %0, %1, %2, %3;"
        : "=r"(d) : "r"(a), "r"(b), "r"(c));
    return d;
}
// clamp + round f32 -> s8
__device__ __forceinline__ int q8(float v) {
    return __float2int_rn(fmaxf(-127.0f, fminf(127.0f, v)));
}

// ---------------------------------------------------------------------------
// Fused prep (pure streaming, no smem):
//   blocks [0,256):   copy x -> out, convert x -> g_xb; first 128 also
//                     init out[:,1024:] = -1.
//   blocks [256,768): elementwise W * log2e -> g_Wb (bf16, [k][n]).
// ---------------------------------------------------------------------------
__global__ __launch_bounds__(256)
void prep_kernel(const float* __restrict__ x, const float* __restrict__ W,
                 float* __restrict__ out) {
    if (blockIdx.x < 256) {
        int t = blockIdx.x * 256 + threadIdx.x;     // handles 8 floats
        int row  = t >> 7;
        int col8 = (t & 127) * 8;
        const float4* src = reinterpret_cast<const float4*>(x + (size_t)row * AA + col8);
        float4 a = src[0], b = src[1];
        float4* dst = reinterpret_cast<float4*>(out + (size_t)row * OUTW + col8);
        dst[0] = a; dst[1] = b;
        __nv_bfloat162 p0 = __float22bfloat162_rn(make_float2(a.x, a.y));
        __nv_bfloat162 p1 = __float22bfloat162_rn(make_float2(a.z, a.w));
        __nv_bfloat162 p2 = __float22bfloat162_rn(make_float2(b.x, b.y));
        __nv_bfloat162 p3 = __float22bfloat162_rn(make_float2(b.z, b.w));
        uint4 o; o.x = b2u(p0); o.y = b2u(p1); o.z = b2u(p2); o.w = b2u(p3);
        reinterpret_cast<uint4*>(g_xb)[t] = o;
        if (blockIdx.x < 128) {
            int idx = blockIdx.x * 256 + threadIdx.x;   // 0..32767
            int i = idx >> 6;
            int b2 = idx & 63;
            out[(size_t)i * OUTW + AA + b2] = -1.0f;
        }
    } else {
        int t = (blockIdx.x - 256) * 256 + threadIdx.x; // handles 8 floats
        const float4* src = reinterpret_cast<const float4*>(W) + 2 * (size_t)t;
        float4 a = src[0], b = src[1];
        __nv_bfloat162 p0 = __float22bfloat162_rn(make_float2(a.x * LOG2E, a.y * LOG2E));
        __nv_bfloat162 p1 = __float22bfloat162_rn(make_float2(a.z * LOG2E, a.w * LOG2E));
        __nv_bfloat162 p2 = __float22bfloat162_rn(make_float2(b.x * LOG2E, b.y * LOG2E));
        __nv_bfloat162 p3 = __float22bfloat162_rn(make_float2(b.z * LOG2E, b.w * LOG2E));
        uint4 o; o.x = b2u(p0); o.y = b2u(p1); o.z = b2u(p2); o.w = b2u(p3);
        reinterpret_cast<uint4*>(g_Wb)[t] = o;
    }
}

// ---------------------------------------------------------------------------
// GEMM via mma.sync bf16 m16n8k16. Block 64x64, 128 threads (4 warps 2x2),
// K chunked by 64, swizzled smem, register prefetch.
// A: row-major [m][k]; B: native [k][n], fragments via ldmatrix.x4.trans.
// Epilogue -> int8 g_Mq (quantized, log2e units).
// ---------------------------------------------------------------------------
#define BK 64
#define NCH (AA / BK)   // 16

__global__ __launch_bounds__(128)
void gemm_mma_kernel() {
    __shared__ __align__(1024) __nv_bfloat16 sA[64 * BK];   // 8 KB  [m-row][k]
    __shared__ __align__(1024) __nv_bfloat16 sB[64 * BK];   // 8 KB  [k-row][n]

    const int tid = threadIdx.x;
    const int wid = tid >> 5;
    const int l   = tid & 31;
    const int mw  = wid & 1;
    const int nw  = wid >> 1;
    const int row0 = blockIdx.y * 64;
    const int col0 = blockIdx.x * 64;

    const uint32_t sA_addr = smem_u32(sA);
    const uint32_t sB_addr = smem_u32(sB);

    float acc[2][4][4];
#pragma unroll
    for (int mt = 0; mt < 2; mt++)
#pragma unroll
        for (int nt = 0; nt < 4; nt++)
#pragma unroll
            for (int e = 0; e < 4; e++) acc[mt][nt][e] = 0.0f;

    uint4 pa[4], pb[4];
#pragma unroll
    for (int s = 0; s < 4; s++) {
        int ch = tid + s * 128;
        int r = ch >> 3, u = ch & 7;
        pa[s] = *reinterpret_cast<const uint4*>(g_xb + (size_t)(row0 + r) * AA + u * 8);
        pb[s] = *reinterpret_cast<const uint4*>(g_Wb + (size_t)r * AA + col0 + u * 8);
    }

    const int aRow0 = ((l >> 3) & 1) * 8 + (l & 7) + mw * 32;
    const int aKsel = (l >> 4);
    const int bRowL = ((l >> 3) & 1) * 8 + (l & 7);   // k-row within 16-step
    const int bUsel = (l >> 4);                        // n 16B-unit selector
    const int swz   = (l & 7);

    for (int c = 0; c < NCH; c++) {
#pragma unroll
        for (int s = 0; s < 4; s++) {
            int ch = tid + s * 128;
            int r = ch >> 3, u = ch & 7;
            uint32_t off = (uint32_t)(r * 128 + ((u ^ (r & 7)) << 4));
            *reinterpret_cast<uint4*>(reinterpret_cast<char*>(sA) + off) = pa[s];
            *reinterpret_cast<uint4*>(reinterpret_cast<char*>(sB) + off) = pb[s];
        }
        __syncthreads();

        if (c + 1 < NCH) {
            int k0 = (c + 1) * BK;
#pragma unroll
            for (int s = 0; s < 4; s++) {
                int ch = tid + s * 128;
                int r = ch >> 3, u = ch & 7;
                pa[s] = *reinterpret_cast<const uint4*>(g_xb + (size_t)(row0 + r) * AA + k0 + u * 8);
                pb[s] = *reinterpret_cast<const uint4*>(g_Wb + (size_t)(k0 + r) * AA + col0 + u * 8);
            }
        }

#pragma unroll
        for (int ks = 0; ks < 4; ks++) {
            uint32_t af[2][4], bf[4][2];
#pragma unroll
            for (int mt = 0; mt < 2; mt++) {
                int row = aRow0 + mt * 16;
                uint32_t u = (uint32_t)(ks * 2 + aKsel);
                uint32_t addr = sA_addr + (uint32_t)(row * 128) + (((u ^ swz)) << 4);
                LDMATRIX_X4(af[mt][0], af[mt][1], af[mt][2], af[mt][3], addr);
            }
#pragma unroll
            for (int h = 0; h < 2; h++) {
                int row = ks * 16 + bRowL;
                uint32_t u = (uint32_t)(nw * 4 + h * 2 + bUsel);
                uint32_t addr = sB_addr + (uint32_t)(row * 128) + (((u ^ (row & 7))) << 4);
                uint32_t r0, r1, r2, r3;
                LDMATRIX_X4_T(r0, r1, r2, r3, addr);
                bf[h * 2 + 0][0] = r0; bf[h * 2 + 0][1] = r1;
                bf[h * 2 + 1][0] = r2; bf[h * 2 + 1][1] = r3;
            }
#pragma unroll
            for (int mt = 0; mt < 2; mt++)
#pragma unroll
                for (int nt = 0; nt < 4; nt++)
                    mma_bf16(acc[mt][nt], af[mt], bf[nt]);
        }
        __syncthreads();
    }

    // Epilogue: quantize to int8, 2 bytes per (row, col-pair).
    // g_Mq byte layout: row*1024 + b*16 + c  (c = component 0..15)
    char* Mq = reinterpret_cast<char*>(g_Mq);
    const int g = l >> 2;
    const int cc2 = (l & 3) * 2;
#pragma unroll
    for (int mt = 0; mt < 2; mt++) {
#pragma unroll
        for (int nt = 0; nt < 4; nt++) {
            int gcol = col0 + nw * 32 + nt * 8 + cc2;
            int b  = gcol >> 4;
            int cc = gcol & 15;
            int rowA = row0 + mw * 32 + mt * 16 + g;
            int v0 = q8(acc[mt][nt][0]), v1 = q8(acc[mt][nt][1]);
            int v2 = q8(acc[mt][nt][2]), v3 = q8(acc[mt][nt][3]);
            unsigned short u01 = (unsigned short)((v0 & 0xFF) | ((v1 & 0xFF) << 8));
            unsigned short u23 = (unsigned short)((v2 & 0xFF) | ((v3 & 0xFF) << 8));
            *reinterpret_cast<unsigned short*>(Mq + (size_t)rowA * 1024 + b * 16 + cc) = u01;
            *reinterpret_cast<unsigned short*>(Mq + (size_t)(rowA + 8) * 1024 + b * 16 + cc) = u23;
        }
    }
}

// ---------------------------------------------------------------------------
// Pairwise via packed-byte SAD. Triangular tiles over 16 groups of 32 rows,
// 136 blocks x 512 threads (single wave). Thread (b = t&63, isp = t>>6):
// owns 4 i-rows, loops 32 j-rows (prefetch depth 2).
// exp2(-SAD) accumulated; atomically added into out[:,1024:] (init -1).
// ---------------------------------------------------------------------------
__global__ __launch_bounds__(512)
void pairwise_kernel(float* __restrict__ out) {
    const int t   = threadIdx.x;
    const int b   = t & 63;
    const int isp = t >> 6;        // 0..7

    // decode triangular tile: offset(g) = g*(33-g)/2 for NGRP=16
    int tt = blockIdx.x;
    int gi = 0;
#pragma unroll
    for (int g = 1; g < NGRP; g++)
        if ((g * (2 * NGRP + 1 - g)) / 2 <= tt) gi = g;
    int gj = gi + (tt - (gi * (2 * NGRP + 1 - gi)) / 2);

    const int i0 = gi * GSZ + isp * 4;
    const int j0 = gj * GSZ;

    __shared__ float red[16][8][BB];   // 32 KB (half of the j-group at a time)

    const uint4* Mq4 = reinterpret_cast<const uint4*>(g_Mq);   // row stride 64 uint4

    // load 4 i-rows (one uint4 each = 16 int8 comps)
    uint4 mi[4];
#pragma unroll
    for (int k = 0; k < 4; k++)
        mi[k] = Mq4[(size_t)(i0 + k) * 64 + b];

    float acc_i[4] = {0.f, 0.f, 0.f, 0.f};

    // prefetch depth 2 on j-rows
    uint4 jb[2];
    jb[0] = Mq4[(size_t)j0 * 64 + b];
    jb[1] = Mq4[(size_t)(j0 + 1) * 64 + b];

    for (int half = 0; half < 2; half++) {
#pragma unroll
        for (int jj = 0; jj < 16; jj++) {
            const int jg = half * 16 + jj;
            uint4 mj = jb[jg & 1];
            if (jg + 2 < GSZ)
                jb[jg & 1] = Mq4[(size_t)(j0 + jg + 2) * 64 + b];

            float e[4];
#pragma unroll
            for (int k = 0; k < 4; k++) {
                int s = vsad4(mj.x, mi[k].x, 0);
                s = vsad4(mj.y, mi[k].y, s);
                s = vsad4(mj.z, mi[k].z, s);
                s = vsad4(mj.w, mi[k].w, s);
                e[k] = ex2(__int2float_rn(-s));
            }
            acc_i[0] += e[0]; acc_i[1] += e[1];
            acc_i[2] += e[2]; acc_i[3] += e[3];
            red[jj][isp][b] = (e[0] + e[1]) + (e[2] + e[3]);
        }
        __syncthreads();
        // j-side flush for this half (off-diagonal tiles only)
        if (gi != gj) {
#pragma unroll
            for (int w = 0; w < 2; w++) {
                int cell = t + w * 512;           // 0..1023
                int jj = cell >> 6;
                int bb = cell & 63;
                float s = red[jj][0][bb] + red[jj][1][bb] + red[jj][2][bb] + red[jj][3][bb]
                        + red[jj][4][bb] + red[jj][5][bb] + red[jj][6][bb] + red[jj][7][bb];
                atomicAdd(out + (size_t)(j0 + half * 16 + jj) * OUTW + AA + bb, s);
            }
        }
        __syncthreads();
    }

    // i-side: atomic add per owned row
#pragma unroll
    for (int k = 0; k < 4; k++)
        atomicAdd(out + (size_t)(i0 + k) * OUTW + AA + b, acc_i[k]);
}

// ---------------------------------------------------------------------------
extern "C" void kernel_launch(void* const* d_in, const int* in_sizes, int n_in,
                              void* d_out, int out_size) {
    const float* x = (const float*)d_in[0];   // (512, 1024)
    const float* T = (const float*)d_in[1];   // (1024, 1024)
    float* out = (float*)d_out;               // (512, 1088)

    prep_kernel<<<768, 256>>>(x, T, out);

    dim3 ggrid(AA / 64, NN / 64);             // (16, 8) = 128 blocks
    gemm_mma_kernel<<<ggrid, 128>>>();

    pairwise_kernel<<<NTILES, 512>>>(out);    // 136 blocks, single wave
}

// round 13
// speedup vs baseline: 2.0046x; 2.0046x over previous
#include <cuda_runtime.h>
#include <cuda_bf16.h>
#include <cstdint>

// Problem constants: N=512, A=1024, B=64, C=16
#define NN   512
#define AA   1024
#define BB   64
#define CC   16
#define OUTW (AA + BB)   // 1088

#define NGRP   16            // row groups of 32
#define GSZ    32
#define NTILES (NGRP * (NGRP + 1) / 2)   // 136

#define LOG2E 1.44269504088896340736f

// ---------------- device scratch ----------------
// M (pre-scaled by log2e) in bf16x2: g_Mb[row*512 + b*8 + c2]
__device__ uint32_t g_Mb[NN * 512];
__device__ __nv_bfloat16 g_xb[NN * AA];     // x in bf16
__device__ __nv_bfloat16 g_Wb[AA * AA];     // W * log2e in bf16, native [k][n]

// ---------------- helpers ----------------
__device__ __forceinline__ uint32_t smem_u32(const void* p) {
    uint32_t a;
    asm("{ .reg .u64 t; cvta.to.shared.u64 t, %1; cvt.u32.u64 %0, t; }" : "=r"(a) : "l"(p));
    return a;
}
#define LDMATRIX_X4(r0, r1, r2, r3, addr) \
    asm volatile("ldmatrix.sync.aligned.m8n8.x4.shared.b16 {%0,%1,%2,%3}, [%4];" \
        : "=r"(r0), "=r"(r1), "=r"(r2), "=r"(r3) : "r"(addr))
#define LDMATRIX_X4_T(r0, r1, r2, r3, addr) \
    asm volatile("ldmatrix.sync.aligned.m8n8.x4.trans.shared.b16 {%0,%1,%2,%3}, [%4];" \
        : "=r"(r0), "=r"(r1), "=r"(r2), "=r"(r3) : "r"(addr))

__device__ __forceinline__ void mma_bf16(float d[4], const uint32_t a[4], const uint32_t b[2]) {
    asm volatile(
        "mma.sync.aligned.m16n8k16.row.col.f32.bf16.bf16.f32 "
        "{%0,%1,%2,%3}, {%4,%5,%6,%7}, {%8,%9}, {%0,%1,%2,%3};"
        : "+f"(d[0]), "+f"(d[1]), "+f"(d[2]), "+f"(d[3])
        : "r"(a[0]), "r"(a[1]), "r"(a[2]), "r"(a[3]), "r"(b[0]), "r"(b[1]));
}

__device__ __forceinline__ __nv_bfloat162 u2b(uint32_t u) {
    return *reinterpret_cast<__nv_bfloat162*>(&u);
}
__device__ __forceinline__ uint32_t b2u(__nv_bfloat162 v) {
    return *reinterpret_cast<uint32_t*>(&v);
}
__device__ __forceinline__ float ex2(float v) {
    float r; asm("ex2.approx.f32 %0, %1;" : "=f"(r) : "f"(v)); return r;
}

// -(L1 over 16 bf16 components held as 8 bf16x2 regs); exact lo/hi extraction.
__device__ __forceinline__ float l1_neg(const uint32_t* mj, const uint32_t* mi) {
    __nv_bfloat162 d0 = __habs2(__hsub2(u2b(mj[0]), u2b(mi[0])));
    __nv_bfloat162 d1 = __habs2(__hsub2(u2b(mj[1]), u2b(mi[1])));
    __nv_bfloat162 d2 = __habs2(__hsub2(u2b(mj[2]), u2b(mi[2])));
    __nv_bfloat162 d3 = __habs2(__hsub2(u2b(mj[3]), u2b(mi[3])));
    __nv_bfloat162 d4 = __habs2(__hsub2(u2b(mj[4]), u2b(mi[4])));
    __nv_bfloat162 d5 = __habs2(__hsub2(u2b(mj[5]), u2b(mi[5])));
    __nv_bfloat162 d6 = __habs2(__hsub2(u2b(mj[6]), u2b(mi[6])));
    __nv_bfloat162 d7 = __habs2(__hsub2(u2b(mj[7]), u2b(mi[7])));
    __nv_bfloat162 s = __hadd2(__hadd2(__hadd2(d0, d1), __hadd2(d2, d3)),
                               __hadd2(__hadd2(d4, d5), __hadd2(d6, d7)));
    uint32_t u = b2u(s);
    float lo = __uint_as_float(u << 16);          // bf16 -> f32 zero-extension: exact
    float hi = __uint_as_float(u & 0xFFFF0000u);
    return (-lo) - hi;                            // FADD with neg modifiers
}

// ---------------------------------------------------------------------------
// Fused prep (pure streaming, no smem):
//   blocks [0,256):   copy x -> out, convert x -> g_xb; first 128 also
//                     init out[:,1024:] = -1.
//   blocks [256,768): elementwise W * log2e -> g_Wb (bf16, [k][n]).
// ---------------------------------------------------------------------------
__global__ __launch_bounds__(256)
void prep_kernel(const float* __restrict__ x, const float* __restrict__ W,
                 float* __restrict__ out) {
    if (blockIdx.x < 256) {
        int t = blockIdx.x * 256 + threadIdx.x;     // handles 8 floats
        int row  = t >> 7;
        int col8 = (t & 127) * 8;
        const float4* src = reinterpret_cast<const float4*>(x + (size_t)row * AA + col8);
        float4 a = src[0], b = src[1];
        float4* dst = reinterpret_cast<float4*>(out + (size_t)row * OUTW + col8);
        dst[0] = a; dst[1] = b;
        __nv_bfloat162 p0 = __float22bfloat162_rn(make_float2(a.x, a.y));
        __nv_bfloat162 p1 = __float22bfloat162_rn(make_float2(a.z, a.w));
        __nv_bfloat162 p2 = __float22bfloat162_rn(make_float2(b.x, b.y));
        __nv_bfloat162 p3 = __float22bfloat162_rn(make_float2(b.z, b.w));
        uint4 o; o.x = b2u(p0); o.y = b2u(p1); o.z = b2u(p2); o.w = b2u(p3);
        reinterpret_cast<uint4*>(g_xb)[t] = o;
        if (blockIdx.x < 128) {
            int idx = blockIdx.x * 256 + threadIdx.x;   // 0..32767
            int i = idx >> 6;
            int b2 = idx & 63;
            out[(size_t)i * OUTW + AA + b2] = -1.0f;
        }
    } else {
        int t = (blockIdx.x - 256) * 256 + threadIdx.x; // handles 8 floats
        const float4* src = reinterpret_cast<const float4*>(W) + 2 * (size_t)t;
        float4 a = src[0], b = src[1];
        __nv_bfloat162 p0 = __float22bfloat162_rn(make_float2(a.x * LOG2E, a.y * LOG2E));
        __nv_bfloat162 p1 = __float22bfloat162_rn(make_float2(a.z * LOG2E, a.w * LOG2E));
        __nv_bfloat162 p2 = __float22bfloat162_rn(make_float2(b.x * LOG2E, b.y * LOG2E));
        __nv_bfloat162 p3 = __float22bfloat162_rn(make_float2(b.z * LOG2E, b.w * LOG2E));
        uint4 o; o.x = b2u(p0); o.y = b2u(p1); o.z = b2u(p2); o.w = b2u(p3);
        reinterpret_cast<uint4*>(g_Wb)[t] = o;
    }
}

// ---------------------------------------------------------------------------
// GEMM via mma.sync bf16 m16n8k16. Block 64x64, 128 threads (4 warps 2x2),
// K chunked by 64, swizzled smem, register prefetch.
// A: row-major [m][k]; B: native [k][n], fragments via ldmatrix.x4.trans.
// Epilogue -> bf16 g_Mb.
// ---------------------------------------------------------------------------
#define BK 64
#define NCH (AA / BK)   // 16

__global__ __launch_bounds__(128)
void gemm_mma_kernel() {
    __shared__ __align__(1024) __nv_bfloat16 sA[64 * BK];   // 8 KB  [m-row][k]
    __shared__ __align__(1024) __nv_bfloat16 sB[64 * BK];   // 8 KB  [k-row][n]

    const int tid = threadIdx.x;
    const int wid = tid >> 5;
    const int l   = tid & 31;
    const int mw  = wid & 1;
    const int nw  = wid >> 1;
    const int row0 = blockIdx.y * 64;
    const int col0 = blockIdx.x * 64;

    const uint32_t sA_addr = smem_u32(sA);
    const uint32_t sB_addr = smem_u32(sB);

    float acc[2][4][4];
#pragma unroll
    for (int mt = 0; mt < 2; mt++)
#pragma unroll
        for (int nt = 0; nt < 4; nt++)
#pragma unroll
            for (int e = 0; e < 4; e++) acc[mt][nt][e] = 0.0f;

    uint4 pa[4], pb[4];
#pragma unroll
    for (int s = 0; s < 4; s++) {
        int ch = tid + s * 128;
        int r = ch >> 3, u = ch & 7;
        pa[s] = *reinterpret_cast<const uint4*>(g_xb + (size_t)(row0 + r) * AA + u * 8);
        pb[s] = *reinterpret_cast<const uint4*>(g_Wb + (size_t)r * AA + col0 + u * 8);
    }

    const int aRow0 = ((l >> 3) & 1) * 8 + (l & 7) + mw * 32;
    const int aKsel = (l >> 4);
    const int bRowL = ((l >> 3) & 1) * 8 + (l & 7);   // k-row within 16-step
    const int bUsel = (l >> 4);                        // n 16B-unit selector
    const int swz   = (l & 7);

    for (int c = 0; c < NCH; c++) {
#pragma unroll
        for (int s = 0; s < 4; s++) {
            int ch = tid + s * 128;
            int r = ch >> 3, u = ch & 7;
            uint32_t off = (uint32_t)(r * 128 + ((u ^ (r & 7)) << 4));
            *reinterpret_cast<uint4*>(reinterpret_cast<char*>(sA) + off) = pa[s];
            *reinterpret_cast<uint4*>(reinterpret_cast<char*>(sB) + off) = pb[s];
        }
        __syncthreads();

        if (c + 1 < NCH) {
            int k0 = (c + 1) * BK;
#pragma unroll
            for (int s = 0; s < 4; s++) {
                int ch = tid + s * 128;
                int r = ch >> 3, u = ch & 7;
                pa[s] = *reinterpret_cast<const uint4*>(g_xb + (size_t)(row0 + r) * AA + k0 + u * 8);
                pb[s] = *reinterpret_cast<const uint4*>(g_Wb + (size_t)(k0 + r) * AA + col0 + u * 8);
            }
        }

#pragma unroll
        for (int ks = 0; ks < 4; ks++) {
            uint32_t af[2][4], bf[4][2];
#pragma unroll
            for (int mt = 0; mt < 2; mt++) {
                int row = aRow0 + mt * 16;
                uint32_t u = (uint32_t)(ks * 2 + aKsel);
                uint32_t addr = sA_addr + (uint32_t)(row * 128) + (((u ^ swz)) << 4);
                LDMATRIX_X4(af[mt][0], af[mt][1], af[mt][2], af[mt][3], addr);
            }
#pragma unroll
            for (int h = 0; h < 2; h++) {
                int row = ks * 16 + bRowL;
                uint32_t u = (uint32_t)(nw * 4 + h * 2 + bUsel);
                uint32_t addr = sB_addr + (uint32_t)(row * 128) + (((u ^ (row & 7))) << 4);
                uint32_t r0, r1, r2, r3;
                LDMATRIX_X4_T(r0, r1, r2, r3, addr);
                bf[h * 2 + 0][0] = r0; bf[h * 2 + 0][1] = r1;
                bf[h * 2 + 1][0] = r2; bf[h * 2 + 1][1] = r3;
            }
#pragma unroll
            for (int mt = 0; mt < 2; mt++)
#pragma unroll
                for (int nt = 0; nt < 4; nt++)
                    mma_bf16(acc[mt][nt], af[mt], bf[nt]);
        }
        __syncthreads();
    }

    // Epilogue: bf16x2 into pairwise layout g_Mb[row*512 + b*8 + c2]
    const int g = l >> 2;
    const int cc2 = (l & 3) * 2;
#pragma unroll
    for (int mt = 0; mt < 2; mt++) {
#pragma unroll
        for (int nt = 0; nt < 4; nt++) {
            int gcol = col0 + nw * 32 + nt * 8 + cc2;
            int b  = gcol >> 4;
            int c2 = (gcol & 15) >> 1;
            int rowA = row0 + mw * 32 + mt * 16 + g;
            __nv_bfloat162 v0 = __float22bfloat162_rn(
                make_float2(acc[mt][nt][0], acc[mt][nt][1]));
            __nv_bfloat162 v1 = __float22bfloat162_rn(
                make_float2(acc[mt][nt][2], acc[mt][nt][3]));
            g_Mb[(size_t)rowA * 512 + b * 8 + c2]       = b2u(v0);
            g_Mb[(size_t)(rowA + 8) * 512 + b * 8 + c2] = b2u(v1);
        }
    }
}

// ---------------------------------------------------------------------------
// Pairwise, triangular tiles over 16 groups of 32 rows. 136 blocks x 1024 thr
// (single wave, 32 warps/SM). Thread (b = t&63, isp = t>>6 in 0..15): owns
// 2 i-rows, loops 32 j-rows (prefetch depth 2). j-side reduced in quarters
// of 8 rows against a 32 KB smem buffer. Results atomically added into
// out[:,1024:] (pre-initialized to -1 by prep).
// ---------------------------------------------------------------------------
__global__ __launch_bounds__(1024)
void pairwise_kernel(float* __restrict__ out) {
    const int t   = threadIdx.x;
    const int b   = t & 63;
    const int isp = t >> 6;        // 0..15

    // decode triangular tile: offset(g) = g*(33-g)/2 for NGRP=16
    int tt = blockIdx.x;
    int gi = 0;
#pragma unroll
    for (int g = 1; g < NGRP; g++)
        if ((g * (2 * NGRP + 1 - g)) / 2 <= tt) gi = g;
    int gj = gi + (tt - (gi * (2 * NGRP + 1 - gi)) / 2);

    const int i0 = gi * GSZ + isp * 2;
    const int j0 = gj * GSZ;

    __shared__ float red[8][16][BB];   // 32 KB (quarter of the j-group)

    const uint4* Mb4 = reinterpret_cast<const uint4*>(g_Mb);

    // load 2 i-rows (8 u32 each)
    uint32_t mi[2][8];
#pragma unroll
    for (int k = 0; k < 2; k++) {
        uint4 v0 = Mb4[(size_t)(i0 + k) * 128 + b * 2];
        uint4 v1 = Mb4[(size_t)(i0 + k) * 128 + b * 2 + 1];
        mi[k][0] = v0.x; mi[k][1] = v0.y; mi[k][2] = v0.z; mi[k][3] = v0.w;
        mi[k][4] = v1.x; mi[k][5] = v1.y; mi[k][6] = v1.z; mi[k][7] = v1.w;
    }

    float acc_i[2] = {0.f, 0.f};

    // prefetch depth 2 on j-rows
    uint32_t jb[2][8];
#pragma unroll
    for (int p = 0; p < 2; p++) {
        uint4 v0 = Mb4[(size_t)(j0 + p) * 128 + b * 2];
        uint4 v1 = Mb4[(size_t)(j0 + p) * 128 + b * 2 + 1];
        jb[p][0] = v0.x; jb[p][1] = v0.y; jb[p][2] = v0.z; jb[p][3] = v0.w;
        jb[p][4] = v1.x; jb[p][5] = v1.y; jb[p][6] = v1.z; jb[p][7] = v1.w;
    }

    for (int q = 0; q < 4; q++) {
#pragma unroll
        for (int jj = 0; jj < 8; jj++) {
            const int jg = q * 8 + jj;
            uint32_t mj[8];
#pragma unroll
            for (int c = 0; c < 8; c++) mj[c] = jb[jg & 1][c];
            if (jg + 2 < GSZ) {
                uint4 v0 = Mb4[(size_t)(j0 + jg + 2) * 128 + b * 2];
                uint4 v1 = Mb4[(size_t)(j0 + jg + 2) * 128 + b * 2 + 1];
                jb[jg & 1][0] = v0.x; jb[jg & 1][1] = v0.y;
                jb[jg & 1][2] = v0.z; jb[jg & 1][3] = v0.w;
                jb[jg & 1][4] = v1.x; jb[jg & 1][5] = v1.y;
                jb[jg & 1][6] = v1.z; jb[jg & 1][7] = v1.w;
            }

            float e0 = ex2(l1_neg(mj, mi[0]));
            float e1 = ex2(l1_neg(mj, mi[1]));
            acc_i[0] += e0;
            acc_i[1] += e1;
            red[jj][isp][b] = e0 + e1;
        }
        __syncthreads();
        // j-side flush for this quarter (off-diagonal tiles only)
        if (gi != gj && t < 512) {
            int jj = t >> 6;
            int bb = t & 63;
            float s = 0.0f;
#pragma unroll
            for (int k = 0; k < 16; k++)
                s += red[jj][k][bb];
            atomicAdd(out + (size_t)(j0 + q * 8 + jj) * OUTW + AA + bb, s);
        }
        __syncthreads();
    }

    // i-side: atomic add per owned row
#pragma unroll
    for (int k = 0; k < 2; k++)
        atomicAdd(out + (size_t)(i0 + k) * OUTW + AA + b, acc_i[k]);
}

// ---------------------------------------------------------------------------
extern "C" void kernel_launch(void* const* d_in, const int* in_sizes, int n_in,
                              void* d_out, int out_size) {
    const float* x = (const float*)d_in[0];   // (512, 1024)
    const float* T = (const float*)d_in[1];   // (1024, 1024)
    float* out = (float*)d_out;               // (512, 1088)

    prep_kernel<<<768, 256>>>(x, T, out);

    dim3 ggrid(AA / 64, NN / 64);             // (16, 8) = 128 blocks
    gemm_mma_kernel<<<ggrid, 128>>>();

    pairwise_kernel<<<NTILES, 1024>>>(out);   // 136 blocks, single wave
}

// round 14
// speedup vs baseline: 2.0811x; 1.0382x over previous
#include <cuda_runtime.h>
#include <cuda_bf16.h>
#include <cstdint>

// Problem constants: N=512, A=1024, B=64, C=16
#define NN   512
#define AA   1024
#define BB   64
#define CC   16
#define OUTW (AA + BB)   // 1088

#define NGRP   16            // row groups of 32
#define GSZ    32
#define NTILES (NGRP * (NGRP + 1) / 2)   // 136

#define LOG2E 1.44269504088896340736f

// ---------------- device scratch ----------------
// M (pre-scaled by log2e) in bf16x2: g_Mb[row*512 + b*8 + c2]
__device__ uint32_t g_Mb[NN * 512];
__device__ __nv_bfloat16 g_xb[NN * AA];     // x in bf16
__device__ __nv_bfloat16 g_Wb[AA * AA];     // W * log2e in bf16, native [k][n]

// ---------------- helpers ----------------
__device__ __forceinline__ uint32_t smem_u32(const void* p) {
    uint32_t a;
    asm("{ .reg .u64 t; cvta.to.shared.u64 t, %1; cvt.u32.u64 %0, t; }" : "=r"(a) : "l"(p));
    return a;
}
#define LDMATRIX_X4(r0, r1, r2, r3, addr) \
    asm volatile("ldmatrix.sync.aligned.m8n8.x4.shared.b16 {%0,%1,%2,%3}, [%4];" \
        : "=r"(r0), "=r"(r1), "=r"(r2), "=r"(r3) : "r"(addr))
#define LDMATRIX_X4_T(r0, r1, r2, r3, addr) \
    asm volatile("ldmatrix.sync.aligned.m8n8.x4.trans.shared.b16 {%0,%1,%2,%3}, [%4];" \
        : "=r"(r0), "=r"(r1), "=r"(r2), "=r"(r3) : "r"(addr))

__device__ __forceinline__ void mma_bf16(float d[4], const uint32_t a[4], const uint32_t b[2]) {
    asm volatile(
        "mma.sync.aligned.m16n8k16.row.col.f32.bf16.bf16.f32 "
        "{%0,%1,%2,%3}, {%4,%5,%6,%7}, {%8,%9}, {%0,%1,%2,%3};"
        : "+f"(d[0]), "+f"(d[1]), "+f"(d[2]), "+f"(d[3])
        : "r"(a[0]), "r"(a[1]), "r"(a[2]), "r"(a[3]), "r"(b[0]), "r"(b[1]));
}

__device__ __forceinline__ __nv_bfloat162 u2b(uint32_t u) {
    return *reinterpret_cast<__nv_bfloat162*>(&u);
}
__device__ __forceinline__ uint32_t b2u(__nv_bfloat162 v) {
    return *reinterpret_cast<uint32_t*>(&v);
}
__device__ __forceinline__ float ex2(float v) {
    float r; asm("ex2.approx.f32 %0, %1;" : "=f"(r) : "f"(v)); return r;
}

// -(L1 over 16 bf16 components held as 8 bf16x2 regs); exact lo/hi extraction.
__device__ __forceinline__ float l1_neg(const uint32_t* mj, const uint32_t* mi) {
    __nv_bfloat162 d0 = __habs2(__hsub2(u2b(mj[0]), u2b(mi[0])));
    __nv_bfloat162 d1 = __habs2(__hsub2(u2b(mj[1]), u2b(mi[1])));
    __nv_bfloat162 d2 = __habs2(__hsub2(u2b(mj[2]), u2b(mi[2])));
    __nv_bfloat162 d3 = __habs2(__hsub2(u2b(mj[3]), u2b(mi[3])));
    __nv_bfloat162 d4 = __habs2(__hsub2(u2b(mj[4]), u2b(mi[4])));
    __nv_bfloat162 d5 = __habs2(__hsub2(u2b(mj[5]), u2b(mi[5])));
    __nv_bfloat162 d6 = __habs2(__hsub2(u2b(mj[6]), u2b(mi[6])));
    __nv_bfloat162 d7 = __habs2(__hsub2(u2b(mj[7]), u2b(mi[7])));
    __nv_bfloat162 s = __hadd2(__hadd2(__hadd2(d0, d1), __hadd2(d2, d3)),
                               __hadd2(__hadd2(d4, d5), __hadd2(d6, d7)));
    uint32_t u = b2u(s);
    float lo = __uint_as_float(u << 16);          // bf16 -> f32 zero-extension: exact
    float hi = __uint_as_float(u & 0xFFFF0000u);
    return (-lo) - hi;                            // FADD with neg modifiers
}

// ---------------------------------------------------------------------------
// Fused prep (pure streaming, no smem):
//   blocks [0,256):   copy x -> out, convert x -> g_xb; first 128 also
//                     init out[:,1024:] = -1.
//   blocks [256,768): elementwise W * log2e -> g_Wb (bf16, [k][n]).
// ---------------------------------------------------------------------------
__global__ __launch_bounds__(256)
void prep_kernel(const float* __restrict__ x, const float* __restrict__ W,
                 float* __restrict__ out) {
    if (blockIdx.x < 256) {
        int t = blockIdx.x * 256 + threadIdx.x;     // handles 8 floats
        int row  = t >> 7;
        int col8 = (t & 127) * 8;
        const float4* src = reinterpret_cast<const float4*>(x + (size_t)row * AA + col8);
        float4 a = src[0], b = src[1];
        float4* dst = reinterpret_cast<float4*>(out + (size_t)row * OUTW + col8);
        dst[0] = a; dst[1] = b;
        __nv_bfloat162 p0 = __float22bfloat162_rn(make_float2(a.x, a.y));
        __nv_bfloat162 p1 = __float22bfloat162_rn(make_float2(a.z, a.w));
        __nv_bfloat162 p2 = __float22bfloat162_rn(make_float2(b.x, b.y));
        __nv_bfloat162 p3 = __float22bfloat162_rn(make_float2(b.z, b.w));
        uint4 o; o.x = b2u(p0); o.y = b2u(p1); o.z = b2u(p2); o.w = b2u(p3);
        reinterpret_cast<uint4*>(g_xb)[t] = o;
        if (blockIdx.x < 128) {
            int idx = blockIdx.x * 256 + threadIdx.x;   // 0..32767
            int i = idx >> 6;
            int b2 = idx & 63;
            out[(size_t)i * OUTW + AA + b2] = -1.0f;
        }
    } else {
        int t = (blockIdx.x - 256) * 256 + threadIdx.x; // handles 8 floats
        const float4* src = reinterpret_cast<const float4*>(W) + 2 * (size_t)t;
        float4 a = src[0], b = src[1];
        __nv_bfloat162 p0 = __float22bfloat162_rn(make_float2(a.x * LOG2E, a.y * LOG2E));
        __nv_bfloat162 p1 = __float22bfloat162_rn(make_float2(a.z * LOG2E, a.w * LOG2E));
        __nv_bfloat162 p2 = __float22bfloat162_rn(make_float2(b.x * LOG2E, b.y * LOG2E));
        __nv_bfloat162 p3 = __float22bfloat162_rn(make_float2(b.z * LOG2E, b.w * LOG2E));
        uint4 o; o.x = b2u(p0); o.y = b2u(p1); o.z = b2u(p2); o.w = b2u(p3);
        reinterpret_cast<uint4*>(g_Wb)[t] = o;
    }
}

// ---------------------------------------------------------------------------
// GEMM via mma.sync bf16 m16n8k16. Block 64x64, 128 threads (4 warps 2x2),
// K chunked by 64, swizzled smem, register prefetch.
// A: row-major [m][k]; B: native [k][n], fragments via ldmatrix.x4.trans.
// Epilogue -> bf16 g_Mb.
// ---------------------------------------------------------------------------
#define BK 64
#define NCH (AA / BK)   // 16

__global__ __launch_bounds__(128)
void gemm_mma_kernel() {
    __shared__ __align__(1024) __nv_bfloat16 sA[64 * BK];   // 8 KB  [m-row][k]
    __shared__ __align__(1024) __nv_bfloat16 sB[64 * BK];   // 8 KB  [k-row][n]

    const int tid = threadIdx.x;
    const int wid = tid >> 5;
    const int l   = tid & 31;
    const int mw  = wid & 1;
    const int nw  = wid >> 1;
    const int row0 = blockIdx.y * 64;
    const int col0 = blockIdx.x * 64;

    const uint32_t sA_addr = smem_u32(sA);
    const uint32_t sB_addr = smem_u32(sB);

    float acc[2][4][4];
#pragma unroll
    for (int mt = 0; mt < 2; mt++)
#pragma unroll
        for (int nt = 0; nt < 4; nt++)
#pragma unroll
            for (int e = 0; e < 4; e++) acc[mt][nt][e] = 0.0f;

    uint4 pa[4], pb[4];
#pragma unroll
    for (int s = 0; s < 4; s++) {
        int ch = tid + s * 128;
        int r = ch >> 3, u = ch & 7;
        pa[s] = *reinterpret_cast<const uint4*>(g_xb + (size_t)(row0 + r) * AA + u * 8);
        pb[s] = *reinterpret_cast<const uint4*>(g_Wb + (size_t)r * AA + col0 + u * 8);
    }

    const int aRow0 = ((l >> 3) & 1) * 8 + (l & 7) + mw * 32;
    const int aKsel = (l >> 4);
    const int bRowL = ((l >> 3) & 1) * 8 + (l & 7);   // k-row within 16-step
    const int bUsel = (l >> 4);                        // n 16B-unit selector
    const int swz   = (l & 7);

    for (int c = 0; c < NCH; c++) {
#pragma unroll
        for (int s = 0; s < 4; s++) {
            int ch = tid + s * 128;
            int r = ch >> 3, u = ch & 7;
            uint32_t off = (uint32_t)(r * 128 + ((u ^ (r & 7)) << 4));
            *reinterpret_cast<uint4*>(reinterpret_cast<char*>(sA) + off) = pa[s];
            *reinterpret_cast<uint4*>(reinterpret_cast<char*>(sB) + off) = pb[s];
        }
        __syncthreads();

        if (c + 1 < NCH) {
            int k0 = (c + 1) * BK;
#pragma unroll
            for (int s = 0; s < 4; s++) {
                int ch = tid + s * 128;
                int r = ch >> 3, u = ch & 7;
                pa[s] = *reinterpret_cast<const uint4*>(g_xb + (size_t)(row0 + r) * AA + k0 + u * 8);
                pb[s] = *reinterpret_cast<const uint4*>(g_Wb + (size_t)(k0 + r) * AA + col0 + u * 8);
            }
        }

#pragma unroll
        for (int ks = 0; ks < 4; ks++) {
            uint32_t af[2][4], bf[4][2];
#pragma unroll
            for (int mt = 0; mt < 2; mt++) {
                int row = aRow0 + mt * 16;
                uint32_t u = (uint32_t)(ks * 2 + aKsel);
                uint32_t addr = sA_addr + (uint32_t)(row * 128) + (((u ^ swz)) << 4);
                LDMATRIX_X4(af[mt][0], af[mt][1], af[mt][2], af[mt][3], addr);
            }
#pragma unroll
            for (int h = 0; h < 2; h++) {
                int row = ks * 16 + bRowL;
                uint32_t u = (uint32_t)(nw * 4 + h * 2 + bUsel);
                uint32_t addr = sB_addr + (uint32_t)(row * 128) + (((u ^ (row & 7))) << 4);
                uint32_t r0, r1, r2, r3;
                LDMATRIX_X4_T(r0, r1, r2, r3, addr);
                bf[h * 2 + 0][0] = r0; bf[h * 2 + 0][1] = r1;
                bf[h * 2 + 1][0] = r2; bf[h * 2 + 1][1] = r3;
            }
#pragma unroll
            for (int mt = 0; mt < 2; mt++)
#pragma unroll
                for (int nt = 0; nt < 4; nt++)
                    mma_bf16(acc[mt][nt], af[mt], bf[nt]);
        }
        __syncthreads();
    }

    // Epilogue: bf16x2 into pairwise layout g_Mb[row*512 + b*8 + c2]
    const int g = l >> 2;
    const int cc2 = (l & 3) * 2;
#pragma unroll
    for (int mt = 0; mt < 2; mt++) {
#pragma unroll
        for (int nt = 0; nt < 4; nt++) {
            int gcol = col0 + nw * 32 + nt * 8 + cc2;
            int b  = gcol >> 4;
            int c2 = (gcol & 15) >> 1;
            int rowA = row0 + mw * 32 + mt * 16 + g;
            __nv_bfloat162 v0 = __float22bfloat162_rn(
                make_float2(acc[mt][nt][0], acc[mt][nt][1]));
            __nv_bfloat162 v1 = __float22bfloat162_rn(
                make_float2(acc[mt][nt][2], acc[mt][nt][3]));
            g_Mb[(size_t)rowA * 512 + b * 8 + c2]       = b2u(v0);
            g_Mb[(size_t)(rowA + 8) * 512 + b * 8 + c2] = b2u(v1);
        }
    }
}

// ---------------------------------------------------------------------------
// Pairwise, triangular tiles over 16 groups of 32 rows. 136 blocks x 512 thr
// (single co-resident wave). Thread (b = t&63, isp = t>>6 in 0..7): owns
// 4 i-rows, loops 32 j-rows with PREFETCH DEPTH 4 (covers L2 latency).
// j-side reduced in two 16-row halves against a 32 KB smem buffer.
// Results atomically added into out[:,1024:] (pre-initialized to -1).
// ---------------------------------------------------------------------------
__global__ __launch_bounds__(512)
void pairwise_kernel(float* __restrict__ out) {
    const int t   = threadIdx.x;
    const int b   = t & 63;
    const int isp = t >> 6;        // 0..7

    // decode triangular tile: offset(g) = g*(33-g)/2 for NGRP=16
    int tt = blockIdx.x;
    int gi = 0;
#pragma unroll
    for (int g = 1; g < NGRP; g++)
        if ((g * (2 * NGRP + 1 - g)) / 2 <= tt) gi = g;
    int gj = gi + (tt - (gi * (2 * NGRP + 1 - gi)) / 2);

    const int i0 = gi * GSZ + isp * 4;
    const int j0 = gj * GSZ;

    __shared__ float red[16][8][BB];   // 32 KB (half of the j-group at a time)

    const uint4* Mb4 = reinterpret_cast<const uint4*>(g_Mb);

    // load 4 i-rows (8 u32 each)
    uint32_t mi[4][8];
#pragma unroll
    for (int k = 0; k < 4; k++) {
        uint4 v0 = Mb4[(size_t)(i0 + k) * 128 + b * 2];
        uint4 v1 = Mb4[(size_t)(i0 + k) * 128 + b * 2 + 1];
        mi[k][0] = v0.x; mi[k][1] = v0.y; mi[k][2] = v0.z; mi[k][3] = v0.w;
        mi[k][4] = v1.x; mi[k][5] = v1.y; mi[k][6] = v1.z; mi[k][7] = v1.w;
    }

    float acc_i[4] = {0.f, 0.f, 0.f, 0.f};

    // prefetch depth 4 on j-rows (covers L2 latency ~240 cyc)
    uint32_t jb[4][8];
#pragma unroll
    for (int p = 0; p < 4; p++) {
        uint4 v0 = Mb4[(size_t)(j0 + p) * 128 + b * 2];
        uint4 v1 = Mb4[(size_t)(j0 + p) * 128 + b * 2 + 1];
        jb[p][0] = v0.x; jb[p][1] = v0.y; jb[p][2] = v0.z; jb[p][3] = v0.w;
        jb[p][4] = v1.x; jb[p][5] = v1.y; jb[p][6] = v1.z; jb[p][7] = v1.w;
    }

    for (int half = 0; half < 2; half++) {
#pragma unroll
        for (int jj = 0; jj < 16; jj++) {
            const int jg = half * 16 + jj;
            uint32_t mj[8];
#pragma unroll
            for (int c = 0; c < 8; c++) mj[c] = jb[jg & 3][c];
            if (jg + 4 < GSZ) {
                uint4 v0 = Mb4[(size_t)(j0 + jg + 4) * 128 + b * 2];
                uint4 v1 = Mb4[(size_t)(j0 + jg + 4) * 128 + b * 2 + 1];
                jb[jg & 3][0] = v0.x; jb[jg & 3][1] = v0.y;
                jb[jg & 3][2] = v0.z; jb[jg & 3][3] = v0.w;
                jb[jg & 3][4] = v1.x; jb[jg & 3][5] = v1.y;
                jb[jg & 3][6] = v1.z; jb[jg & 3][7] = v1.w;
            }

            float e0 = ex2(l1_neg(mj, mi[0]));
            float e1 = ex2(l1_neg(mj, mi[1]));
            float e2 = ex2(l1_neg(mj, mi[2]));
            float e3 = ex2(l1_neg(mj, mi[3]));
            acc_i[0] += e0; acc_i[1] += e1; acc_i[2] += e2; acc_i[3] += e3;
            red[jj][isp][b] = (e0 + e1) + (e2 + e3);
        }
        __syncthreads();
        // j-side flush for this half (off-diagonal tiles only)
        if (gi != gj) {
#pragma unroll
            for (int w = 0; w < 2; w++) {
                int cell = t + w * 512;           // 0..1023
                int jj = cell >> 6;
                int bb = cell & 63;
                float s = red[jj][0][bb] + red[jj][1][bb] + red[jj][2][bb] + red[jj][3][bb]
                        + red[jj][4][bb] + red[jj][5][bb] + red[jj][6][bb] + red[jj][7][bb];
                atomicAdd(out + (size_t)(j0 + half * 16 + jj) * OUTW + AA + bb, s);
            }
        }
        __syncthreads();
    }

    // i-side: atomic add per owned row
#pragma unroll
    for (int k = 0; k < 4; k++)
        atomicAdd(out + (size_t)(i0 + k) * OUTW + AA + b, acc_i[k]);
}

// ---------------------------------------------------------------------------
extern "C" void kernel_launch(void* const* d_in, const int* in_sizes, int n_in,
                              void* d_out, int out_size) {
    const float* x = (const float*)d_in[0];   // (512, 1024)
    const float* T = (const float*)d_in[1];   // (1024, 1024)
    float* out = (float*)d_out;               // (512, 1088)

    prep_kernel<<<768, 256>>>(x, T, out);

    dim3 ggrid(AA / 64, NN / 64);             // (16, 8) = 128 blocks
    gemm_mma_kernel<<<ggrid, 128>>>();

    pairwise_kernel<<<NTILES, 512>>>(out);    // 136 blocks, single wave
}

// round 15
// speedup vs baseline: 2.0831x; 1.0010x over previous
#include <cuda_runtime.h>
#include <cuda_bf16.h>
#include <cstdint>

// Problem constants: N=512, A=1024, B=64, C=16
#define NN   512
#define AA   1024
#define BB   64
#define CC   16
#define OUTW (AA + BB)   // 1088

#define NGRP   16            // row groups of 32
#define GSZ    32
#define NTILES (NGRP * (NGRP + 1) / 2)   // 136
#define NB     NTILES        // grid size (single wave on 148 SMs)
#define NTHR   512

#define LOG2E 1.44269504088896340736f

// ---------------- device scratch ----------------
__device__ uint32_t g_Mb[NN * 512];          // M*log2e, bf16x2 [row][b*8+c2]
__device__ __nv_bfloat16 g_xb[NN * AA];      // x in bf16
__device__ __nv_bfloat16 g_Wb[AA * AA];      // W*log2e in bf16, native [k][n]
__device__ volatile unsigned g_bar[2];       // monotonic grid-barrier counters

// ---------------- helpers ----------------
__device__ __forceinline__ uint32_t smem_u32(const void* p) {
    uint32_t a;
    asm("{ .reg .u64 t; cvta.to.shared.u64 t, %1; cvt.u32.u64 %0, t; }" : "=r"(a) : "l"(p));
    return a;
}
#define LDMATRIX_X4(r0, r1, r2, r3, addr) \
    asm volatile("ldmatrix.sync.aligned.m8n8.x4.shared.b16 {%0,%1,%2,%3}, [%4];" \
        : "=r"(r0), "=r"(r1), "=r"(r2), "=r"(r3) : "r"(addr))
#define LDMATRIX_X4_T(r0, r1, r2, r3, addr) \
    asm volatile("ldmatrix.sync.aligned.m8n8.x4.trans.shared.b16 {%0,%1,%2,%3}, [%4];" \
        : "=r"(r0), "=r"(r1), "=r"(r2), "=r"(r3) : "r"(addr))
#define BAR1_128() asm volatile("bar.sync 1, 128;" ::: "memory")

__device__ __forceinline__ void mma_bf16(float d[4], const uint32_t a[4], const uint32_t b[2]) {
    asm volatile(
        "mma.sync.aligned.m16n8k16.row.col.f32.bf16.bf16.f32 "
        "{%0,%1,%2,%3}, {%4,%5,%6,%7}, {%8,%9}, {%0,%1,%2,%3};"
        : "+f"(d[0]), "+f"(d[1]), "+f"(d[2]), "+f"(d[3])
        : "r"(a[0]), "r"(a[1]), "r"(a[2]), "r"(a[3]), "r"(b[0]), "r"(b[1]));
}

__device__ __forceinline__ __nv_bfloat162 u2b(uint32_t u) {
    return *reinterpret_cast<__nv_bfloat162*>(&u);
}
__device__ __forceinline__ uint32_t b2u(__nv_bfloat162 v) {
    return *reinterpret_cast<uint32_t*>(&v);
}
__device__ __forceinline__ float ex2(float v) {
    float r; asm("ex2.approx.f32 %0, %1;" : "=f"(r) : "f"(v)); return r;
}

// -(L1 over 16 bf16 comps in 8 bf16x2 regs); exact lo/hi extraction.
__device__ __forceinline__ float l1_neg(const uint32_t* mj, const uint32_t* mi) {
    __nv_bfloat162 d0 = __habs2(__hsub2(u2b(mj[0]), u2b(mi[0])));
    __nv_bfloat162 d1 = __habs2(__hsub2(u2b(mj[1]), u2b(mi[1])));
    __nv_bfloat162 d2 = __habs2(__hsub2(u2b(mj[2]), u2b(mi[2])));
    __nv_bfloat162 d3 = __habs2(__hsub2(u2b(mj[3]), u2b(mi[3])));
    __nv_bfloat162 d4 = __habs2(__hsub2(u2b(mj[4]), u2b(mi[4])));
    __nv_bfloat162 d5 = __habs2(__hsub2(u2b(mj[5]), u2b(mi[5])));
    __nv_bfloat162 d6 = __habs2(__hsub2(u2b(mj[6]), u2b(mi[6])));
    __nv_bfloat162 d7 = __habs2(__hsub2(u2b(mj[7]), u2b(mi[7])));
    __nv_bfloat162 s = __hadd2(__hadd2(__hadd2(d0, d1), __hadd2(d2, d3)),
                               __hadd2(__hadd2(d4, d5), __hadd2(d6, d7)));
    uint32_t u = b2u(s);
    float lo = __uint_as_float(u << 16);          // bf16 -> f32 zero-extension: exact
    float hi = __uint_as_float(u & 0xFFFF0000u);
    return (-lo) - hi;                            // FADD with neg modifiers
}

// Grid barrier: monotonic ticket counter (replay-safe, never reset).
__device__ __forceinline__ void grid_barrier(int which) {
    __syncthreads();
    if (threadIdx.x == 0) {
        __threadfence();
        unsigned ticket = atomicAdd((unsigned*)&g_bar[which], 1u);
        unsigned target = ticket - (ticket % NB) + NB;
        while (g_bar[which] < target) { __nanosleep(64); }
    }
    __syncthreads();
}

// ---------------------------------------------------------------------------
// Single fused kernel: prep -> barrier -> GEMM -> barrier -> pairwise.
// 136 blocks x 512 threads, single co-resident wave.
// ---------------------------------------------------------------------------
__global__ __launch_bounds__(NTHR)
void fused_kernel(const float* __restrict__ x, const float* __restrict__ W,
                  float* __restrict__ out) {
    __shared__ __align__(1024) char smem_buf[32768];   // phase1: sA|sB, phase2: red

    const int tid = threadIdx.x;
    const int gt  = blockIdx.x * NTHR + tid;           // 0..69631

    // ================= Phase 0: prep =================
    // x: 65536 units of 8 floats -> copy to out + convert to g_xb
    if (gt < 65536) {
        int row  = gt >> 7;
        int col8 = (gt & 127) * 8;
        const float4* src = reinterpret_cast<const float4*>(x + (size_t)row * AA + col8);
        float4 a = src[0], b = src[1];
        float4* dst = reinterpret_cast<float4*>(out + (size_t)row * OUTW + col8);
        dst[0] = a; dst[1] = b;
        __nv_bfloat162 p0 = __float22bfloat162_rn(make_float2(a.x, a.y));
        __nv_bfloat162 p1 = __float22bfloat162_rn(make_float2(a.z, a.w));
        __nv_bfloat162 p2 = __float22bfloat162_rn(make_float2(b.x, b.y));
        __nv_bfloat162 p3 = __float22bfloat162_rn(make_float2(b.z, b.w));
        uint4 o; o.x = b2u(p0); o.y = b2u(p1); o.z = b2u(p2); o.w = b2u(p3);
        reinterpret_cast<uint4*>(g_xb)[gt] = o;
    }
    // W: 131072 units of 8 floats -> *log2e, convert to g_Wb
    for (int u = gt; u < 131072; u += NB * NTHR) {
        const float4* src = reinterpret_cast<const float4*>(W) + 2 * (size_t)u;
        float4 a = src[0], b = src[1];
        __nv_bfloat162 p0 = __float22bfloat162_rn(make_float2(a.x * LOG2E, a.y * LOG2E));
        __nv_bfloat162 p1 = __float22bfloat162_rn(make_float2(a.z * LOG2E, a.w * LOG2E));
        __nv_bfloat162 p2 = __float22bfloat162_rn(make_float2(b.x * LOG2E, b.y * LOG2E));
        __nv_bfloat162 p3 = __float22bfloat162_rn(make_float2(b.z * LOG2E, b.w * LOG2E));
        uint4 o; o.x = b2u(p0); o.y = b2u(p1); o.z = b2u(p2); o.w = b2u(p3);
        reinterpret_cast<uint4*>(g_Wb)[u] = o;
    }
    // out tail init: 32768 floats = -1
    if (gt < 32768) {
        int i = gt >> 6, b2 = gt & 63;
        out[(size_t)i * OUTW + AA + b2] = -1.0f;
    }

    grid_barrier(0);

    // ================= Phase 1: GEMM (blocks 0..127, threads 0..127) ========
    if (blockIdx.x < 128 && tid < 128) {
        __nv_bfloat16* sA = reinterpret_cast<__nv_bfloat16*>(smem_buf);          // 8 KB
        __nv_bfloat16* sB = reinterpret_cast<__nv_bfloat16*>(smem_buf + 8192);   // 8 KB
        const int wid = tid >> 5;
        const int l   = tid & 31;
        const int mw  = wid & 1;
        const int nw  = wid >> 1;
        const int row0 = (blockIdx.x >> 4) * 64;   // 8 m-tiles
        const int col0 = (blockIdx.x & 15) * 64;   // 16 n-tiles

        const uint32_t sA_addr = smem_u32(sA);
        const uint32_t sB_addr = smem_u32(sB);

        float acc[2][4][4];
#pragma unroll
        for (int mt = 0; mt < 2; mt++)
#pragma unroll
            for (int nt = 0; nt < 4; nt++)
#pragma unroll
                for (int e = 0; e < 4; e++) acc[mt][nt][e] = 0.0f;

        uint4 pa[4], pb[4];
#pragma unroll
        for (int s = 0; s < 4; s++) {
            int ch = tid + s * 128;
            int r = ch >> 3, u = ch & 7;
            pa[s] = *reinterpret_cast<const uint4*>(g_xb + (size_t)(row0 + r) * AA + u * 8);
            pb[s] = *reinterpret_cast<const uint4*>(g_Wb + (size_t)r * AA + col0 + u * 8);
        }

        const int aRow0 = ((l >> 3) & 1) * 8 + (l & 7) + mw * 32;
        const int aKsel = (l >> 4);
        const int bRowL = ((l >> 3) & 1) * 8 + (l & 7);
        const int bUsel = (l >> 4);
        const int swz   = (l & 7);

        for (int c = 0; c < 16; c++) {            // 16 K-chunks of 64
#pragma unroll
            for (int s = 0; s < 4; s++) {
                int ch = tid + s * 128;
                int r = ch >> 3, u = ch & 7;
                uint32_t off = (uint32_t)(r * 128 + ((u ^ (r & 7)) << 4));
                *reinterpret_cast<uint4*>(reinterpret_cast<char*>(sA) + off) = pa[s];
                *reinterpret_cast<uint4*>(reinterpret_cast<char*>(sB) + off) = pb[s];
            }
            BAR1_128();

            if (c + 1 < 16) {
                int k0 = (c + 1) * 64;
#pragma unroll
                for (int s = 0; s < 4; s++) {
                    int ch = tid + s * 128;
                    int r = ch >> 3, u = ch & 7;
                    pa[s] = *reinterpret_cast<const uint4*>(g_xb + (size_t)(row0 + r) * AA + k0 + u * 8);
                    pb[s] = *reinterpret_cast<const uint4*>(g_Wb + (size_t)(k0 + r) * AA + col0 + u * 8);
                }
            }

#pragma unroll
            for (int ks = 0; ks < 4; ks++) {
                uint32_t af[2][4], bf[4][2];
#pragma unroll
                for (int mt = 0; mt < 2; mt++) {
                    int row = aRow0 + mt * 16;
                    uint32_t u = (uint32_t)(ks * 2 + aKsel);
                    uint32_t addr = sA_addr + (uint32_t)(row * 128) + (((u ^ swz)) << 4);
                    LDMATRIX_X4(af[mt][0], af[mt][1], af[mt][2], af[mt][3], addr);
                }
#pragma unroll
                for (int h = 0; h < 2; h++) {
                    int row = ks * 16 + bRowL;
                    uint32_t u = (uint32_t)(nw * 4 + h * 2 + bUsel);
                    uint32_t addr = sB_addr + (uint32_t)(row * 128) + (((u ^ (row & 7))) << 4);
                    uint32_t r0, r1, r2, r3;
                    LDMATRIX_X4_T(r0, r1, r2, r3, addr);
                    bf[h * 2 + 0][0] = r0; bf[h * 2 + 0][1] = r1;
                    bf[h * 2 + 1][0] = r2; bf[h * 2 + 1][1] = r3;
                }
#pragma unroll
                for (int mt = 0; mt < 2; mt++)
#pragma unroll
                    for (int nt = 0; nt < 4; nt++)
                        mma_bf16(acc[mt][nt], af[mt], bf[nt]);
            }
            BAR1_128();
        }

        // Epilogue: bf16x2 into pairwise layout g_Mb[row*512 + b*8 + c2]
        const int g = l >> 2;
        const int cc2 = (l & 3) * 2;
#pragma unroll
        for (int mt = 0; mt < 2; mt++) {
#pragma unroll
            for (int nt = 0; nt < 4; nt++) {
                int gcol = col0 + nw * 32 + nt * 8 + cc2;
                int b  = gcol >> 4;
                int c2 = (gcol & 15) >> 1;
                int rowA = row0 + mw * 32 + mt * 16 + g;
                __nv_bfloat162 v0 = __float22bfloat162_rn(
                    make_float2(acc[mt][nt][0], acc[mt][nt][1]));
                __nv_bfloat162 v1 = __float22bfloat162_rn(
                    make_float2(acc[mt][nt][2], acc[mt][nt][3]));
                g_Mb[(size_t)rowA * 512 + b * 8 + c2]       = b2u(v0);
                g_Mb[(size_t)(rowA + 8) * 512 + b * 8 + c2] = b2u(v1);
            }
        }
    }

    grid_barrier(1);

    // ================= Phase 2: pairwise =================
    {
        float (*red)[8][BB] = reinterpret_cast<float (*)[8][BB]>(smem_buf); // [16][8][64]
        const int b   = tid & 63;
        const int isp = tid >> 6;      // 0..7

        int tt = blockIdx.x;
        int gi = 0;
#pragma unroll
        for (int g = 1; g < NGRP; g++)
            if ((g * (2 * NGRP + 1 - g)) / 2 <= tt) gi = g;
        int gj = gi + (tt - (gi * (2 * NGRP + 1 - gi)) / 2);

        const int i0 = gi * GSZ + isp * 4;
        const int j0 = gj * GSZ;

        const uint4* Mb4 = reinterpret_cast<const uint4*>(g_Mb);

        uint32_t mi[4][8];
#pragma unroll
        for (int k = 0; k < 4; k++) {
            uint4 v0 = Mb4[(size_t)(i0 + k) * 128 + b * 2];
            uint4 v1 = Mb4[(size_t)(i0 + k) * 128 + b * 2 + 1];
            mi[k][0] = v0.x; mi[k][1] = v0.y; mi[k][2] = v0.z; mi[k][3] = v0.w;
            mi[k][4] = v1.x; mi[k][5] = v1.y; mi[k][6] = v1.z; mi[k][7] = v1.w;
        }

        float acc_i[4] = {0.f, 0.f, 0.f, 0.f};

        uint32_t jb[2][8];
#pragma unroll
        for (int p = 0; p < 2; p++) {
            uint4 v0 = Mb4[(size_t)(j0 + p) * 128 + b * 2];
            uint4 v1 = Mb4[(size_t)(j0 + p) * 128 + b * 2 + 1];
            jb[p][0] = v0.x; jb[p][1] = v0.y; jb[p][2] = v0.z; jb[p][3] = v0.w;
            jb[p][4] = v1.x; jb[p][5] = v1.y; jb[p][6] = v1.z; jb[p][7] = v1.w;
        }

        for (int half = 0; half < 2; half++) {
#pragma unroll
            for (int jj = 0; jj < 16; jj++) {
                const int jg = half * 16 + jj;
                uint32_t mj[8];
#pragma unroll
                for (int c = 0; c < 8; c++) mj[c] = jb[jg & 1][c];
                if (jg + 2 < GSZ) {
                    uint4 v0 = Mb4[(size_t)(j0 + jg + 2) * 128 + b * 2];
                    uint4 v1 = Mb4[(size_t)(j0 + jg + 2) * 128 + b * 2 + 1];
                    jb[jg & 1][0] = v0.x; jb[jg & 1][1] = v0.y;
                    jb[jg & 1][2] = v0.z; jb[jg & 1][3] = v0.w;
                    jb[jg & 1][4] = v1.x; jb[jg & 1][5] = v1.y;
                    jb[jg & 1][6] = v1.z; jb[jg & 1][7] = v1.w;
                }

                float e0 = ex2(l1_neg(mj, mi[0]));
                float e1 = ex2(l1_neg(mj, mi[1]));
                float e2 = ex2(l1_neg(mj, mi[2]));
                float e3 = ex2(l1_neg(mj, mi[3]));
                acc_i[0] += e0; acc_i[1] += e1; acc_i[2] += e2; acc_i[3] += e3;
                red[jj][isp][b] = (e0 + e1) + (e2 + e3);
            }
            __syncthreads();
            if (gi != gj) {
#pragma unroll
                for (int w = 0; w < 2; w++) {
                    int cell = tid + w * 512;
                    int jj = cell >> 6;
                    int bb = cell & 63;
                    float s = red[jj][0][bb] + red[jj][1][bb] + red[jj][2][bb] + red[jj][3][bb]
                            + red[jj][4][bb] + red[jj][5][bb] + red[jj][6][bb] + red[jj][7][bb];
                    atomicAdd(out + (size_t)(j0 + half * 16 + jj) * OUTW + AA + bb, s);
                }
            }
            __syncthreads();
        }

#pragma unroll
        for (int k = 0; k < 4; k++)
            atomicAdd(out + (size_t)(i0 + k) * OUTW + AA + b, acc_i[k]);
    }
}

// ---------------------------------------------------------------------------
extern "C" void kernel_launch(void* const* d_in, const int* in_sizes, int n_in,
                              void* d_out, int out_size) {
    const float* x = (const float*)d_in[0];   // (512, 1024)
    const float* T = (const float*)d_in[1];   // (1024, 1024)
    float* out = (float*)d_out;               // (512, 1088)

    fused_kernel<<<NB, NTHR>>>(x, T, out);    // single launch, single wave
}

// round 16
// speedup vs baseline: 2.3941x; 1.1493x over previous
#include <cuda_runtime.h>
#include <cuda_fp16.h>
#include <cstdint>

// Problem constants: N=512, A=1024, B=64, C=16
#define NN   512
#define AA   1024
#define BB   64
#define CC   16
#define OUTW (AA + BB)   // 1088

#define NGRP   16            // row groups of 32
#define GSZ    32
#define NTILES (NGRP * (NGRP + 1) / 2)   // 136

#define LOG2E 1.44269504088896340736f

// ---------------- device scratch ----------------
// M (pre-scaled by log2e) in fp16x2: g_Mh[row*512 + b*8 + c2]
__device__ uint32_t g_Mh[NN * 512];
__device__ __half g_xh[NN * AA];     // x in fp16
__device__ __half g_Wh[AA * AA];     // W * log2e in fp16, native [k][n]

// ---------------- helpers ----------------
__device__ __forceinline__ uint32_t smem_u32(const void* p) {
    uint32_t a;
    asm("{ .reg .u64 t; cvta.to.shared.u64 t, %1; cvt.u32.u64 %0, t; }" : "=r"(a) : "l"(p));
    return a;
}
#define LDMATRIX_X4(r0, r1, r2, r3, addr) \
    asm volatile("ldmatrix.sync.aligned.m8n8.x4.shared.b16 {%0,%1,%2,%3}, [%4];" \
        : "=r"(r0), "=r"(r1), "=r"(r2), "=r"(r3) : "r"(addr))
#define LDMATRIX_X4_T(r0, r1, r2, r3, addr) \
    asm volatile("ldmatrix.sync.aligned.m8n8.x4.trans.shared.b16 {%0,%1,%2,%3}, [%4];" \
        : "=r"(r0), "=r"(r1), "=r"(r2), "=r"(r3) : "r"(addr))

__device__ __forceinline__ void mma_f16(float d[4], const uint32_t a[4], const uint32_t b[2]) {
    asm volatile(
        "mma.sync.aligned.m16n8k16.row.col.f32.f16.f16.f32 "
        "{%0,%1,%2,%3}, {%4,%5,%6,%7}, {%8,%9}, {%0,%1,%2,%3};"
        : "+f"(d[0]), "+f"(d[1]), "+f"(d[2]), "+f"(d[3])
        : "r"(a[0]), "r"(a[1]), "r"(a[2]), "r"(a[3]), "r"(b[0]), "r"(b[1]));
}

__device__ __forceinline__ __half2 u2h(uint32_t u) {
    return *reinterpret_cast<__half2*>(&u);
}
__device__ __forceinline__ uint32_t h2u(__half2 v) {
    return *reinterpret_cast<uint32_t*>(&v);
}
__device__ __forceinline__ float ex2(float v) {
    float r; asm("ex2.approx.f32 %0, %1;" : "=f"(r) : "f"(v)); return r;
}

// -(L1 over 16 fp16 components held as 8 half2 regs).
__device__ __forceinline__ float l1_neg(const uint32_t* mj, const uint32_t* mi) {
    __half2 d0 = __habs2(__hsub2(u2h(mj[0]), u2h(mi[0])));
    __half2 d1 = __habs2(__hsub2(u2h(mj[1]), u2h(mi[1])));
    __half2 d2 = __habs2(__hsub2(u2h(mj[2]), u2h(mi[2])));
    __half2 d3 = __habs2(__hsub2(u2h(mj[3]), u2h(mi[3])));
    __half2 d4 = __habs2(__hsub2(u2h(mj[4]), u2h(mi[4])));
    __half2 d5 = __habs2(__hsub2(u2h(mj[5]), u2h(mi[5])));
    __half2 d6 = __habs2(__hsub2(u2h(mj[6]), u2h(mi[6])));
    __half2 d7 = __habs2(__hsub2(u2h(mj[7]), u2h(mi[7])));
    __half2 s = __hadd2(__hadd2(__hadd2(d0, d1), __hadd2(d2, d3)),
                        __hadd2(__hadd2(d4, d5), __hadd2(d6, d7)));
    float2 f = __half22float2(s);
    return (-f.x) - f.y;                          // FADD with neg modifiers
}

// ---------------------------------------------------------------------------
// Fused prep (pure streaming, no smem):
//   blocks [0,256):   copy x -> out, convert x -> g_xh; first 128 also
//                     init out[:,1024:] = -1.
//   blocks [256,768): elementwise W * log2e -> g_Wh (fp16, [k][n]).
// ---------------------------------------------------------------------------
__global__ __launch_bounds__(256)
void prep_kernel(const float* __restrict__ x, const float* __restrict__ W,
                 float* __restrict__ out) {
    if (blockIdx.x < 256) {
        int t = blockIdx.x * 256 + threadIdx.x;     // handles 8 floats
        int row  = t >> 7;
        int col8 = (t & 127) * 8;
        const float4* src = reinterpret_cast<const float4*>(x + (size_t)row * AA + col8);
        float4 a = src[0], b = src[1];
        float4* dst = reinterpret_cast<float4*>(out + (size_t)row * OUTW + col8);
        dst[0] = a; dst[1] = b;
        __half2 p0 = __float22half2_rn(make_float2(a.x, a.y));
        __half2 p1 = __float22half2_rn(make_float2(a.z, a.w));
        __half2 p2 = __float22half2_rn(make_float2(b.x, b.y));
        __half2 p3 = __float22half2_rn(make_float2(b.z, b.w));
        uint4 o; o.x = h2u(p0); o.y = h2u(p1); o.z = h2u(p2); o.w = h2u(p3);
        reinterpret_cast<uint4*>(g_xh)[t] = o;
        if (blockIdx.x < 128) {
            int idx = blockIdx.x * 256 + threadIdx.x;   // 0..32767
            int i = idx >> 6;
            int b2 = idx & 63;
            out[(size_t)i * OUTW + AA + b2] = -1.0f;
        }
    } else {
        int t = (blockIdx.x - 256) * 256 + threadIdx.x; // handles 8 floats
        const float4* src = reinterpret_cast<const float4*>(W) + 2 * (size_t)t;
        float4 a = src[0], b = src[1];
        __half2 p0 = __float22half2_rn(make_float2(a.x * LOG2E, a.y * LOG2E));
        __half2 p1 = __float22half2_rn(make_float2(a.z * LOG2E, a.w * LOG2E));
        __half2 p2 = __float22half2_rn(make_float2(b.x * LOG2E, b.y * LOG2E));
        __half2 p3 = __float22half2_rn(make_float2(b.z * LOG2E, b.w * LOG2E));
        uint4 o; o.x = h2u(p0); o.y = h2u(p1); o.z = h2u(p2); o.w = h2u(p3);
        reinterpret_cast<uint4*>(g_Wh)[t] = o;
    }
}

// ---------------------------------------------------------------------------
// GEMM via mma.sync fp16 m16n8k16. Block 64x64, 128 threads (4 warps 2x2),
// K chunked by 64, swizzled smem, register prefetch.
// A: row-major [m][k]; B: native [k][n], fragments via ldmatrix.x4.trans.
// Epilogue -> fp16 g_Mh.
// ---------------------------------------------------------------------------
#define BK 64
#define NCH (AA / BK)   // 16

__global__ __launch_bounds__(128)
void gemm_mma_kernel() {
    __shared__ __align__(1024) __half sA[64 * BK];   // 8 KB  [m-row][k]
    __shared__ __align__(1024) __half sB[64 * BK];   // 8 KB  [k-row][n]

    const int tid = threadIdx.x;
    const int wid = tid >> 5;
    const int l   = tid & 31;
    const int mw  = wid & 1;
    const int nw  = wid >> 1;
    const int row0 = blockIdx.y * 64;
    const int col0 = blockIdx.x * 64;

    const uint32_t sA_addr = smem_u32(sA);
    const uint32_t sB_addr = smem_u32(sB);

    float acc[2][4][4];
#pragma unroll
    for (int mt = 0; mt < 2; mt++)
#pragma unroll
        for (int nt = 0; nt < 4; nt++)
#pragma unroll
            for (int e = 0; e < 4; e++) acc[mt][nt][e] = 0.0f;

    uint4 pa[4], pb[4];
#pragma unroll
    for (int s = 0; s < 4; s++) {
        int ch = tid + s * 128;
        int r = ch >> 3, u = ch & 7;
        pa[s] = *reinterpret_cast<const uint4*>(g_xh + (size_t)(row0 + r) * AA + u * 8);
        pb[s] = *reinterpret_cast<const uint4*>(g_Wh + (size_t)r * AA + col0 + u * 8);
    }

    const int aRow0 = ((l >> 3) & 1) * 8 + (l & 7) + mw * 32;
    const int aKsel = (l >> 4);
    const int bRowL = ((l >> 3) & 1) * 8 + (l & 7);   // k-row within 16-step
    const int bUsel = (l >> 4);                        // n 16B-unit selector
    const int swz   = (l & 7);

    for (int c = 0; c < NCH; c++) {
#pragma unroll
        for (int s = 0; s < 4; s++) {
            int ch = tid + s * 128;
            int r = ch >> 3, u = ch & 7;
            uint32_t off = (uint32_t)(r * 128 + ((u ^ (r & 7)) << 4));
            *reinterpret_cast<uint4*>(reinterpret_cast<char*>(sA) + off) = pa[s];
            *reinterpret_cast<uint4*>(reinterpret_cast<char*>(sB) + off) = pb[s];
        }
        __syncthreads();

        if (c + 1 < NCH) {
            int k0 = (c + 1) * BK;
#pragma unroll
            for (int s = 0; s < 4; s++) {
                int ch = tid + s * 128;
                int r = ch >> 3, u = ch & 7;
                pa[s] = *reinterpret_cast<const uint4*>(g_xh + (size_t)(row0 + r) * AA + k0 + u * 8);
                pb[s] = *reinterpret_cast<const uint4*>(g_Wh + (size_t)(k0 + r) * AA + col0 + u * 8);
            }
        }

#pragma unroll
        for (int ks = 0; ks < 4; ks++) {
            uint32_t af[2][4], bf[4][2];
#pragma unroll
            for (int mt = 0; mt < 2; mt++) {
                int row = aRow0 + mt * 16;
                uint32_t u = (uint32_t)(ks * 2 + aKsel);
                uint32_t addr = sA_addr + (uint32_t)(row * 128) + (((u ^ swz)) << 4);
                LDMATRIX_X4(af[mt][0], af[mt][1], af[mt][2], af[mt][3], addr);
            }
#pragma unroll
            for (int h = 0; h < 2; h++) {
                int row = ks * 16 + bRowL;
                uint32_t u = (uint32_t)(nw * 4 + h * 2 + bUsel);
                uint32_t addr = sB_addr + (uint32_t)(row * 128) + (((u ^ (row & 7))) << 4);
                uint32_t r0, r1, r2, r3;
                LDMATRIX_X4_T(r0, r1, r2, r3, addr);
                bf[h * 2 + 0][0] = r0; bf[h * 2 + 0][1] = r1;
                bf[h * 2 + 1][0] = r2; bf[h * 2 + 1][1] = r3;
            }
#pragma unroll
            for (int mt = 0; mt < 2; mt++)
#pragma unroll
                for (int nt = 0; nt < 4; nt++)
                    mma_f16(acc[mt][nt], af[mt], bf[nt]);
        }
        __syncthreads();
    }

    // Epilogue: fp16x2 into pairwise layout g_Mh[row*512 + b*8 + c2]
    const int g = l >> 2;
    const int cc2 = (l & 3) * 2;
#pragma unroll
    for (int mt = 0; mt < 2; mt++) {
#pragma unroll
        for (int nt = 0; nt < 4; nt++) {
            int gcol = col0 + nw * 32 + nt * 8 + cc2;
            int b  = gcol >> 4;
            int c2 = (gcol & 15) >> 1;
            int rowA = row0 + mw * 32 + mt * 16 + g;
            __half2 v0 = __float22half2_rn(make_float2(acc[mt][nt][0], acc[mt][nt][1]));
            __half2 v1 = __float22half2_rn(make_float2(acc[mt][nt][2], acc[mt][nt][3]));
            g_Mh[(size_t)rowA * 512 + b * 8 + c2]       = h2u(v0);
            g_Mh[(size_t)(rowA + 8) * 512 + b * 8 + c2] = h2u(v1);
        }
    }
}

// ---------------------------------------------------------------------------
// Pairwise, triangular tiles over 16 groups of 32 rows. 136 blocks x 512 thr
// (single co-resident wave). Thread (b = t&63, isp = t>>6 in 0..7): owns
// 4 i-rows, loops 32 j-rows (prefetch depth 2). j-side reduced in two
// 16-row halves against a 32 KB smem buffer. Results atomically added
// into out[:,1024:] (pre-initialized to -1 by prep).
// ---------------------------------------------------------------------------
__global__ __launch_bounds__(512)
void pairwise_kernel(float* __restrict__ out) {
    const int t   = threadIdx.x;
    const int b   = t & 63;
    const int isp = t >> 6;        // 0..7

    // decode triangular tile: offset(g) = g*(33-g)/2 for NGRP=16
    int tt = blockIdx.x;
    int gi = 0;
#pragma unroll
    for (int g = 1; g < NGRP; g++)
        if ((g * (2 * NGRP + 1 - g)) / 2 <= tt) gi = g;
    int gj = gi + (tt - (gi * (2 * NGRP + 1 - gi)) / 2);

    const int i0 = gi * GSZ + isp * 4;
    const int j0 = gj * GSZ;

    __shared__ float red[16][8][BB];   // 32 KB (half of the j-group at a time)

    const uint4* Mh4 = reinterpret_cast<const uint4*>(g_Mh);

    // load 4 i-rows (8 u32 each)
    uint32_t mi[4][8];
#pragma unroll
    for (int k = 0; k < 4; k++) {
        uint4 v0 = Mh4[(size_t)(i0 + k) * 128 + b * 2];
        uint4 v1 = Mh4[(size_t)(i0 + k) * 128 + b * 2 + 1];
        mi[k][0] = v0.x; mi[k][1] = v0.y; mi[k][2] = v0.z; mi[k][3] = v0.w;
        mi[k][4] = v1.x; mi[k][5] = v1.y; mi[k][6] = v1.z; mi[k][7] = v1.w;
    }

    float acc_i[4] = {0.f, 0.f, 0.f, 0.f};

    // prefetch depth 2 on j-rows
    uint32_t jb[2][8];
#pragma unroll
    for (int p = 0; p < 2; p++) {
        uint4 v0 = Mh4[(size_t)(j0 + p) * 128 + b * 2];
        uint4 v1 = Mh4[(size_t)(j0 + p) * 128 + b * 2 + 1];
        jb[p][0] = v0.x; jb[p][1] = v0.y; jb[p][2] = v0.z; jb[p][3] = v0.w;
        jb[p][4] = v1.x; jb[p][5] = v1.y; jb[p][6] = v1.z; jb[p][7] = v1.w;
    }

    for (int half = 0; half < 2; half++) {
#pragma unroll
        for (int jj = 0; jj < 16; jj++) {
            const int jg = half * 16 + jj;
            uint32_t mj[8];
#pragma unroll
            for (int c = 0; c < 8; c++) mj[c] = jb[jg & 1][c];
            if (jg + 2 < GSZ) {
                uint4 v0 = Mh4[(size_t)(j0 + jg + 2) * 128 + b * 2];
                uint4 v1 = Mh4[(size_t)(j0 + jg + 2) * 128 + b * 2 + 1];
                jb[jg & 1][0] = v0.x; jb[jg & 1][1] = v0.y;
                jb[jg & 1][2] = v0.z; jb[jg & 1][3] = v0.w;
                jb[jg & 1][4] = v1.x; jb[jg & 1][5] = v1.y;
                jb[jg & 1][6] = v1.z; jb[jg & 1][7] = v1.w;
            }

            float e0 = ex2(l1_neg(mj, mi[0]));
            float e1 = ex2(l1_neg(mj, mi[1]));
            float e2 = ex2(l1_neg(mj, mi[2]));
            float e3 = ex2(l1_neg(mj, mi[3]));
            acc_i[0] += e0; acc_i[1] += e1; acc_i[2] += e2; acc_i[3] += e3;
            red[jj][isp][b] = (e0 + e1) + (e2 + e3);
        }
        __syncthreads();
        // j-side flush for this half (off-diagonal tiles only)
        if (gi != gj) {
#pragma unroll
            for (int w = 0; w < 2; w++) {
                int cell = t + w * 512;           // 0..1023
                int jj = cell >> 6;
                int bb = cell & 63;
                float s = red[jj][0][bb] + red[jj][1][bb] + red[jj][2][bb] + red[jj][3][bb]
                        + red[jj][4][bb] + red[jj][5][bb] + red[jj][6][bb] + red[jj][7][bb];
                atomicAdd(out + (size_t)(j0 + half * 16 + jj) * OUTW + AA + bb, s);
            }
        }
        __syncthreads();
    }

    // i-side: atomic add per owned row
#pragma unroll
    for (int k = 0; k < 4; k++)
        atomicAdd(out + (size_t)(i0 + k) * OUTW + AA + b, acc_i[k]);
}

// ---------------------------------------------------------------------------
extern "C" void kernel_launch(void* const* d_in, const int* in_sizes, int n_in,
                              void* d_out, int out_size) {
    const float* x = (const float*)d_in[0];   // (512, 1024)
    const float* T = (const float*)d_in[1];   // (1024, 1024)
    float* out = (float*)d_out;               // (512, 1088)

    prep_kernel<<<768, 256>>>(x, T, out);

    dim3 ggrid(AA / 64, NN / 64);             // (16, 8) = 128 blocks
    gemm_mma_kernel<<<ggrid, 128>>>();

    pairwise_kernel<<<NTILES, 512>>>(out);    // 136 blocks, single wave
}